// round 5
// baseline (speedup 1.0000x reference)
#include <cuda_runtime.h>
#include <cuda_bf16.h>

// Problem constants
#define B_    8
#define N_    8192
#define DIN   13
#define M_    2048
#define KNB   32
// R = 0.2 (python double); R*R = 0.04000000000000001 -> f32 = 0.04f
#define R2    0.04f

// Output layout (single float32 buffer, outputs concatenated in return order):
//   x_out  [B][M][128]  floats
//   pos_s  [B][M][3]    floats
//   batch_s[B][M]       floats (values 0..7, exact)
#define X_OUT_OFF 0
#define POS_S_OFF (B_ * M_ * 128)            // 2097152
#define BATCH_OFF (POS_S_OFF + B_ * M_ * 3)  // 2146304

// ---------------------------------------------------------------------------
// Distance with NO fma contraction: must bit-match jnp.sum((a-b)**2, -1)
// assumed order (dx*dx + dy*dy) + dz*dz
// ---------------------------------------------------------------------------
__device__ __forceinline__ float d2_exact(float ax, float ay, float az,
                                          float bx, float by, float bz) {
    float dx = ax - bx, dy = ay - by, dz = az - bz;
    return __fadd_rn(__fadd_rn(__fmul_rn(dx, dx), __fmul_rn(dy, dy)),
                     __fmul_rn(dz, dz));
}

// ===========================================================================
// Kernel A: farthest point sampling, 1 CTA per batch element.
// 1024 threads, 8 points per thread held in registers (coords + running min
// distance). One __syncthreads per iteration (double-buffered candidate
// table); every warp redundantly reduces the 32 warp candidates so the block
// winner is known by all threads without a second barrier.
// Writes pos_s and batch_s directly into the output buffer.
// ===========================================================================
#define FPS_THREADS 1024
#define PPT (N_ / FPS_THREADS)   // 8

__global__ void __launch_bounds__(FPS_THREADS)
fps_kernel(const float* __restrict__ pos, float* __restrict__ out) {
    const int b = blockIdx.x;
    const int t = threadIdx.x;
    const float* posb = pos + (size_t)b * N_ * 3;

    __shared__ float s_wv[2][32];
    __shared__ int   s_wi[2][32];

    float px[PPT], py[PPT], pz[PPT], mind[PPT];
#pragma unroll
    for (int k = 0; k < PPT; k++) {
        int g = t + k * FPS_THREADS;
        px[k]   = posb[g * 3 + 0];
        py[k]   = posb[g * 3 + 1];
        pz[k]   = posb[g * 3 + 2];
        mind[k] = 1e10f;
    }

    // First sample is index 0.
    float qx = posb[0], qy = posb[1], qz = posb[2];
    if (t == 0) {
        size_t o = POS_S_OFF + ((size_t)b * M_) * 3;
        out[o + 0] = qx; out[o + 1] = qy; out[o + 2] = qz;
        out[BATCH_OFF + (size_t)b * M_] = (float)b;
    }

    const int lane = t & 31;
    const int wid  = t >> 5;

    for (int it = 1; it < M_; it++) {
        // Update running mins against last selected point; track local argmax
        // (tie-break: smallest global index, ensured by strict > and
        // ascending k).
        float bv = -1.0f;
        int   bi = 0;
#pragma unroll
        for (int k = 0; k < PPT; k++) {
            float d  = d2_exact(px[k], py[k], pz[k], qx, qy, qz);
            float mv = fminf(mind[k], d);
            mind[k]  = mv;
            if (mv > bv) { bv = mv; bi = t + k * FPS_THREADS; }
        }
        // Warp reduce (lexicographic max on (value, -index)).
#pragma unroll
        for (int off = 16; off; off >>= 1) {
            float ov = __shfl_xor_sync(0xffffffffu, bv, off);
            int   oi = __shfl_xor_sync(0xffffffffu, bi, off);
            if (ov > bv || (ov == bv && oi < bi)) { bv = ov; bi = oi; }
        }
        const int buf = it & 1;
        if (lane == 0) { s_wv[buf][wid] = bv; s_wi[buf][wid] = bi; }
        __syncthreads();
        // Every warp reduces the 32 warp-candidates -> all threads learn win.
        bv = s_wv[buf][lane];
        bi = s_wi[buf][lane];
#pragma unroll
        for (int off = 16; off; off >>= 1) {
            float ov = __shfl_xor_sync(0xffffffffu, bv, off);
            int   oi = __shfl_xor_sync(0xffffffffu, bi, off);
            if (ov > bv || (ov == bv && oi < bi)) { bv = ov; bi = oi; }
        }
        const int win = bi;
        qx = posb[win * 3 + 0];   // broadcast LDG, L1-resident after warmup
        qy = posb[win * 3 + 1];
        qz = posb[win * 3 + 2];
        if (t == 0) {
            size_t o = POS_S_OFF + ((size_t)b * M_ + it) * 3;
            out[o + 0] = qx; out[o + 1] = qy; out[o + 2] = qz;
            out[BATCH_OFF + (size_t)b * M_ + it] = (float)b;
        }
    }
}

// ===========================================================================
// Kernel B: radius ball query (first K by index) + gather + 2-layer MLP +
// masked max over neighbors. One warp per center, lane = neighbor slot.
// Weights transposed in smem; layer1 fully unrolled (h1 in registers);
// layer2 reads W2^T rows via LDS.128; per-output warp butterfly max.
// ===========================================================================
#define WPB 8   // warps per block

__global__ void __launch_bounds__(WPB * 32)
sa_kernel(const float* __restrict__ x, const float* __restrict__ pos,
          const float* __restrict__ W1, const float* __restrict__ b1,
          const float* __restrict__ W2, const float* __restrict__ b2,
          float* __restrict__ out) {
    __shared__ __align__(16) float sW1[64][16];    // W1^T:  sW1[j][k] = W1[k][j]
    __shared__ float sb1[64];
    __shared__ __align__(16) float sW2[128][64];   // W2^T:  sW2[j][k] = W2[k][j]
    __shared__ float sb2[128];
    __shared__ int   s_nbr[WPB][KNB];

    const int tid = threadIdx.x;
    for (int i = tid; i < 64 * 16; i += WPB * 32) {
        int j = i >> 4, k = i & 15;
        sW1[j][k] = W1[k * 64 + j];
    }
    for (int i = tid; i < 128 * 64; i += WPB * 32) {
        int j = i >> 6, k = i & 63;
        sW2[j][k] = W2[k * 128 + j];
    }
    if (tid < 64)  sb1[tid] = b1[tid];
    if (tid < 128) sb2[tid] = b2[tid];
    __syncthreads();

    const int warp = tid >> 5;
    const int lane = tid & 31;
    const int c    = blockIdx.x * WPB + warp;   // center id, 0..B*M-1
    const int b    = c >> 11;                   // M_ = 2048
    const float* posb = pos + (size_t)b * N_ * 3;
    const float* xb   = x   + (size_t)b * N_ * DIN;

    // Center coordinates (written by fps_kernel).
    const float cx = out[POS_S_OFF + (size_t)c * 3 + 0];
    const float cy = out[POS_S_OFF + (size_t)c * 3 + 1];
    const float cz = out[POS_S_OFF + (size_t)c * 3 + 2];

    // --- Ball query: first KNB in-ball points by ascending index ----------
    int count = 0;
    for (int base = 0; base < N_ && count < KNB; base += 32) {
        const int n = base + lane;
        float d = d2_exact(posb[n * 3 + 0], posb[n * 3 + 1], posb[n * 3 + 2],
                           cx, cy, cz);
        const bool within = (d <= R2);
        const unsigned mask = __ballot_sync(0xffffffffu, within);
        const int pre = __popc(mask & ((1u << lane) - 1u));
        if (within && (count + pre) < KNB) s_nbr[warp][count + pre] = n;
        count += __popc(mask);
        if (count > KNB) count = KNB;
    }
    __syncwarp();
    const bool valid = (lane < count);
    const int  nbr   = valid ? s_nbr[warp][lane] : s_nbr[warp][0];

    // --- Gather features ---------------------------------------------------
    float f[16];
#pragma unroll
    for (int k = 0; k < DIN; k++) f[k] = xb[(size_t)nbr * DIN + k];
    f[13] = posb[nbr * 3 + 0] - cx;
    f[14] = posb[nbr * 3 + 1] - cy;
    f[15] = posb[nbr * 3 + 2] - cz;

    // --- Layer 1: 16 -> 64, ReLU (fully unrolled so h1 stays in regs) ------
    float h1[64];
#pragma unroll
    for (int j = 0; j < 64; j++) {
        float acc = sb1[j];
        const float4* w = reinterpret_cast<const float4*>(&sW1[j][0]);
#pragma unroll
        for (int k4 = 0; k4 < 4; k4++) {
            float4 w4 = w[k4];
            acc = fmaf(f[4 * k4 + 0], w4.x, acc);
            acc = fmaf(f[4 * k4 + 1], w4.y, acc);
            acc = fmaf(f[4 * k4 + 2], w4.z, acc);
            acc = fmaf(f[4 * k4 + 3], w4.w, acc);
        }
        h1[j] = fmaxf(acc, 0.0f);
    }

    // --- Layer 2: 64 -> 128, ReLU, masked warp-max over neighbor slots -----
    float r0, r1, r2, r3;
#pragma unroll
    for (int jo = 0; jo < 4; jo++) {
#pragma unroll 1
        for (int ji = 0; ji < 32; ji++) {
            const int j = jo * 32 + ji;
            float acc = sb2[j];
            const float4* w = reinterpret_cast<const float4*>(&sW2[j][0]);
#pragma unroll
            for (int k4 = 0; k4 < 16; k4++) {
                float4 w4 = w[k4];
                acc = fmaf(h1[4 * k4 + 0], w4.x, acc);
                acc = fmaf(h1[4 * k4 + 1], w4.y, acc);
                acc = fmaf(h1[4 * k4 + 2], w4.z, acc);
                acc = fmaf(h1[4 * k4 + 3], w4.w, acc);
            }
            acc = fmaxf(acc, 0.0f);
            // invalid slots contribute 0: safe because ReLU >= 0 and the
            // center itself is always a valid neighbor (d^2 = 0 <= R^2).
            acc = valid ? acc : 0.0f;
#pragma unroll
            for (int off = 16; off; off >>= 1)
                acc = fmaxf(acc, __shfl_xor_sync(0xffffffffu, acc, off));
            if (lane == ji) {
                if (jo == 0) r0 = acc;
                else if (jo == 1) r1 = acc;
                else if (jo == 2) r2 = acc;
                else r3 = acc;
            }
        }
    }

    float* o = out + X_OUT_OFF + (size_t)c * 128;
    o[lane +  0] = r0;
    o[lane + 32] = r1;
    o[lane + 64] = r2;
    o[lane + 96] = r3;
}

// ===========================================================================
extern "C" void kernel_launch(void* const* d_in, const int* in_sizes, int n_in,
                              void* d_out, int out_size) {
    (void)in_sizes; (void)n_in; (void)out_size;
    const float* x   = (const float*)d_in[0];   // [B, N, 13]
    const float* pos = (const float*)d_in[1];   // [B, N, 3]
    // d_in[2] = batch (int32) — always broadcast arange(B), recomputed directly
    const float* W1  = (const float*)d_in[3];   // [16, 64]
    const float* b1  = (const float*)d_in[4];   // [64]
    const float* W2  = (const float*)d_in[5];   // [64, 128]
    const float* b2  = (const float*)d_in[6];   // [128]
    float* out = (float*)d_out;

    fps_kernel<<<B_, FPS_THREADS>>>(pos, out);
    sa_kernel<<<(B_ * M_) / WPB, WPB * 32>>>(x, pos, W1, b1, W2, b2, out);
}

// round 6
// speedup vs baseline: 1.2466x; 1.2466x over previous
#include <cuda_runtime.h>
#include <cuda_bf16.h>

// Problem constants
#define B_    8
#define N_    8192
#define DIN   13
#define M_    2048
#define KNB   32
#define R2    0.04f

// Output layout (single float32 buffer, outputs concatenated in return order):
//   x_out  [B][M][128]  floats
//   pos_s  [B][M][3]    floats
//   batch_s[B][M]       floats (values 0..7, exact)
#define X_OUT_OFF 0
#define POS_S_OFF (B_ * M_ * 128)            // 2097152
#define BATCH_OFF (POS_S_OFF + B_ * M_ * 3)  // 2146304

// ---------------------------------------------------------------------------
// Distance with NO fma contraction: must bit-match jnp.sum((a-b)**2, -1)
// ---------------------------------------------------------------------------
__device__ __forceinline__ float d2_exact(float ax, float ay, float az,
                                          float bx, float by, float bz) {
    float dx = ax - bx, dy = ay - by, dz = az - bz;
    return __fadd_rn(__fadd_rn(__fmul_rn(dx, dx), __fmul_rn(dy, dy)),
                     __fmul_rn(dz, dz));
}

__device__ __forceinline__ unsigned smem_u32(const void* p) {
    return (unsigned)__cvta_generic_to_shared(p);
}

// ===========================================================================
// Kernel A: farthest point sampling, cluster of 8 CTAs per batch element.
// 8 CTAs x 256 threads = 2048 threads per cloud, 4 points/thread in regs.
// Per iteration:
//   - update running mins, per-thread argmax (tie -> smallest index)
//   - warp reduce via redux.sync (max valbits, then min idx among ties)
//   - block reduce via one smem stage + redux.sync
//   - cluster reduce: 8 threads broadcast block winner to every peer's
//     DSMEM slot (st.shared::cluster + mbarrier.arrive.release.cluster),
//     all threads wait on local mbarrier (count=8), redux over 8 slots.
// Distances >= 0, so float bits are monotonic under unsigned compare.
// ===========================================================================
#define FPS_CTAS 8
#define FPS_THR  256
#define FPS_TOT  (FPS_CTAS * FPS_THR)   // 2048
#define FPS_PPT  (N_ / FPS_TOT)         // 4

__global__ void __launch_bounds__(FPS_THR)
__cluster_dims__(FPS_CTAS, 1, 1)
fps_kernel(const float* __restrict__ pos, float* __restrict__ out) {
    const int rank = blockIdx.x % FPS_CTAS;
    const int b    = blockIdx.x / FPS_CTAS;
    const int tid  = threadIdx.x;
    const int lane = tid & 31;
    const int wid  = tid >> 5;
    const float* posb = pos + (size_t)b * N_ * 3;

    __shared__ unsigned long long s_mbar;
    __shared__ uint2              s_wslot[2][FPS_THR / 32];
    __shared__ unsigned long long s_cslot[2][FPS_CTAS];

    const unsigned mbar_addr = smem_u32(&s_mbar);
    if (tid == 0) {
        asm volatile("mbarrier.init.shared.b64 [%0], %1;"
                     :: "r"(mbar_addr), "r"(FPS_CTAS) : "memory");
    }
    __syncthreads();
    // All cluster mbarriers initialized before any peer arrives on them.
    asm volatile("barrier.cluster.arrive.aligned;" ::: "memory");
    asm volatile("barrier.cluster.wait.aligned;" ::: "memory");

    float px[FPS_PPT], py[FPS_PPT], pz[FPS_PPT], mind[FPS_PPT];
    const int tg = rank * FPS_THR + tid;    // thread id within the cloud
#pragma unroll
    for (int k = 0; k < FPS_PPT; k++) {
        int g = tg + k * FPS_TOT;
        px[k]   = posb[g * 3 + 0];
        py[k]   = posb[g * 3 + 1];
        pz[k]   = posb[g * 3 + 2];
        mind[k] = 1e10f;
    }

    // First sample is index 0.
    float qx = posb[0], qy = posb[1], qz = posb[2];
    if (rank == 0 && tid == 0) {
        size_t o = POS_S_OFF + ((size_t)b * M_) * 3;
        out[o + 0] = qx; out[o + 1] = qy; out[o + 2] = qz;
        out[BATCH_OFF + (size_t)b * M_] = (float)b;
    }

    for (int it = 1; it < M_; it++) {
        const int buf = it & 1;

        // --- per-thread update + argmax (smallest index on ties) ----------
        float bv = -1.0f; int bi = 0;
#pragma unroll
        for (int k = 0; k < FPS_PPT; k++) {
            float d  = d2_exact(px[k], py[k], pz[k], qx, qy, qz);
            float mv = fminf(mind[k], d);
            mind[k]  = mv;
            if (mv > bv) { bv = mv; bi = tg + k * FPS_TOT; }
        }
        unsigned vb = __float_as_uint(bv);   // bv >= 0 -> monotonic bits

        // --- warp reduce: max value, then min index among ties ------------
        unsigned wmax = __reduce_max_sync(0xffffffffu, vb);
        unsigned cand = (vb == wmax) ? (unsigned)bi : 0xffffffffu;
        unsigned widx = __reduce_min_sync(0xffffffffu, cand);
        if (lane == 0) s_wslot[buf][wid] = make_uint2(wmax, widx);
        __syncthreads();

        // --- block reduce over 8 warp slots (all warps redundantly) -------
        uint2 ws = s_wslot[buf][lane & (FPS_THR / 32 - 1)];
        unsigned bmax = __reduce_max_sync(0xffffffffu, ws.x);
        cand = (ws.x == bmax) ? ws.y : 0xffffffffu;
        unsigned bidx = __reduce_min_sync(0xffffffffu, cand);

        // --- cluster exchange: broadcast block winner to all 8 peers ------
        if (tid < FPS_CTAS) {
            unsigned long long key =
                ((unsigned long long)bmax << 32) | (unsigned long long)bidx;
            unsigned slot = smem_u32(&s_cslot[buf][rank]);
            asm volatile(
                "{\n\t.reg .b32 ra, rb;\n\t"
                "mapa.shared::cluster.u32 ra, %0, %2;\n\t"
                "st.shared::cluster.b64 [ra], %1;\n\t"
                "mapa.shared::cluster.u32 rb, %3, %2;\n\t"
                "mbarrier.arrive.release.cluster.shared::cluster.b64 _, [rb];\n\t"
                "}"
                :: "r"(slot), "l"(key), "r"(tid), "r"(mbar_addr) : "memory");
        }
        // wait for 8 arrivals; phase parity alternates per iteration
        {
            unsigned parity = (unsigned)((it - 1) & 1);
            asm volatile(
                "{\n\t.reg .pred P1;\n\t"
                "WAIT_%=:\n\t"
                "mbarrier.try_wait.parity.acquire.cluster.shared::cta.b64 P1, [%0], %1;\n\t"
                "@P1 bra DONE_%=;\n\t"
                "bra WAIT_%=;\n\t"
                "DONE_%=:\n\t}"
                :: "r"(mbar_addr), "r"(parity) : "memory");
        }

        // --- cluster reduce over 8 slots (all threads redundantly) --------
        unsigned long long cs = s_cslot[buf][lane & (FPS_CTAS - 1)];
        unsigned cv = (unsigned)(cs >> 32);
        unsigned ci = (unsigned)cs;
        unsigned gmax = __reduce_max_sync(0xffffffffu, cv);
        cand = (cv == gmax) ? ci : 0xffffffffu;
        unsigned gidx = __reduce_min_sync(0xffffffffu, cand);

        qx = posb[gidx * 3 + 0];   // broadcast load, L1-resident after warmup
        qy = posb[gidx * 3 + 1];
        qz = posb[gidx * 3 + 2];
        if (rank == 0 && tid == 0) {
            size_t o = POS_S_OFF + ((size_t)b * M_ + it) * 3;
            out[o + 0] = qx; out[o + 1] = qy; out[o + 2] = qz;
            out[BATCH_OFF + (size_t)b * M_ + it] = (float)b;
        }
    }

    // No peer may have outstanding DSMEM traffic at exit (all arrivals for
    // the last phase were consumed by the wait), but close the cluster
    // cleanly anyway.
    asm volatile("barrier.cluster.arrive.aligned;" ::: "memory");
    asm volatile("barrier.cluster.wait.aligned;" ::: "memory");
}

// ===========================================================================
// Kernel B: radius ball query (first K by index) + gather + 2-layer MLP +
// masked max over neighbors. One warp per center, lane = neighbor slot.
// Layer-2 uses dual accumulator chains and redux.sync max (outputs are
// >= 0 after ReLU, so f32 bits are monotonic under unsigned max).
// ===========================================================================
#define WPB 8   // warps per block

__global__ void __launch_bounds__(WPB * 32)
sa_kernel(const float* __restrict__ x, const float* __restrict__ pos,
          const float* __restrict__ W1, const float* __restrict__ b1,
          const float* __restrict__ W2, const float* __restrict__ b2,
          float* __restrict__ out) {
    __shared__ __align__(16) float sW1[64][16];    // W1^T
    __shared__ float sb1[64];
    __shared__ __align__(16) float sW2[128][64];   // W2^T
    __shared__ float sb2[128];
    __shared__ int   s_nbr[WPB][KNB];

    const int tid = threadIdx.x;
    for (int i = tid; i < 64 * 16; i += WPB * 32) {
        int j = i >> 4, k = i & 15;
        sW1[j][k] = W1[k * 64 + j];
    }
    for (int i = tid; i < 128 * 64; i += WPB * 32) {
        int j = i >> 6, k = i & 63;
        sW2[j][k] = W2[k * 128 + j];
    }
    if (tid < 64)  sb1[tid] = b1[tid];
    if (tid < 128) sb2[tid] = b2[tid];
    __syncthreads();

    const int warp = tid >> 5;
    const int lane = tid & 31;
    const int c    = blockIdx.x * WPB + warp;   // center id, 0..B*M-1
    const int b    = c >> 11;                   // M_ = 2048
    const float* posb = pos + (size_t)b * N_ * 3;
    const float* xb   = x   + (size_t)b * N_ * DIN;

    const float cx = out[POS_S_OFF + (size_t)c * 3 + 0];
    const float cy = out[POS_S_OFF + (size_t)c * 3 + 1];
    const float cz = out[POS_S_OFF + (size_t)c * 3 + 2];

    // --- Ball query: first KNB in-ball points by ascending index ----------
    int count = 0;
    for (int base = 0; base < N_ && count < KNB; base += 32) {
        const int n = base + lane;
        float d = d2_exact(posb[n * 3 + 0], posb[n * 3 + 1], posb[n * 3 + 2],
                           cx, cy, cz);
        const bool within = (d <= R2);
        const unsigned mask = __ballot_sync(0xffffffffu, within);
        const int pre = __popc(mask & ((1u << lane) - 1u));
        if (within && (count + pre) < KNB) s_nbr[warp][count + pre] = n;
        count += __popc(mask);
        if (count > KNB) count = KNB;
    }
    __syncwarp();
    const bool valid = (lane < count);
    const int  nbr   = valid ? s_nbr[warp][lane] : s_nbr[warp][0];

    // --- Gather features ---------------------------------------------------
    float f[16];
#pragma unroll
    for (int k = 0; k < DIN; k++) f[k] = xb[(size_t)nbr * DIN + k];
    f[13] = posb[nbr * 3 + 0] - cx;
    f[14] = posb[nbr * 3 + 1] - cy;
    f[15] = posb[nbr * 3 + 2] - cz;

    // --- Layer 1: 16 -> 64, ReLU (h1 stays in registers) -------------------
    float h1[64];
#pragma unroll
    for (int j = 0; j < 64; j++) {
        float acc = sb1[j];
        const float4* w = reinterpret_cast<const float4*>(&sW1[j][0]);
#pragma unroll
        for (int k4 = 0; k4 < 4; k4++) {
            float4 w4 = w[k4];
            acc = fmaf(f[4 * k4 + 0], w4.x, acc);
            acc = fmaf(f[4 * k4 + 1], w4.y, acc);
            acc = fmaf(f[4 * k4 + 2], w4.z, acc);
            acc = fmaf(f[4 * k4 + 3], w4.w, acc);
        }
        h1[j] = fmaxf(acc, 0.0f);
    }

    // --- Layer 2: 64 -> 128, ReLU, masked warp-max (redux.sync) ------------
    float r0, r1, r2, r3;
#pragma unroll
    for (int jo = 0; jo < 4; jo++) {
#pragma unroll 1
        for (int ji = 0; ji < 32; ji++) {
            const int j = jo * 32 + ji;
            float a0 = sb2[j], a1 = 0.0f;
            const float4* w = reinterpret_cast<const float4*>(&sW2[j][0]);
#pragma unroll
            for (int k4 = 0; k4 < 8; k4++) {
                float4 wA = w[k4];
                float4 wB = w[k4 + 8];
                a0 = fmaf(h1[4 * k4 + 0],      wA.x, a0);
                a0 = fmaf(h1[4 * k4 + 1],      wA.y, a0);
                a0 = fmaf(h1[4 * k4 + 2],      wA.z, a0);
                a0 = fmaf(h1[4 * k4 + 3],      wA.w, a0);
                a1 = fmaf(h1[32 + 4 * k4 + 0], wB.x, a1);
                a1 = fmaf(h1[32 + 4 * k4 + 1], wB.y, a1);
                a1 = fmaf(h1[32 + 4 * k4 + 2], wB.z, a1);
                a1 = fmaf(h1[32 + 4 * k4 + 3], wB.w, a1);
            }
            float acc = fmaxf(a0 + a1, 0.0f);
            // invalid slots contribute 0: safe because ReLU >= 0 and the
            // center itself is always a valid neighbor (d^2 = 0 <= R^2).
            if (!valid) acc = 0.0f;
            // acc >= 0 -> f32 bits monotonic under unsigned max
            unsigned red = __reduce_max_sync(0xffffffffu, __float_as_uint(acc));
            if (lane == ji) {
                float rv = __uint_as_float(red);
                if (jo == 0) r0 = rv;
                else if (jo == 1) r1 = rv;
                else if (jo == 2) r2 = rv;
                else r3 = rv;
            }
        }
    }

    float* o = out + X_OUT_OFF + (size_t)c * 128;
    o[lane +  0] = r0;
    o[lane + 32] = r1;
    o[lane + 64] = r2;
    o[lane + 96] = r3;
}

// ===========================================================================
extern "C" void kernel_launch(void* const* d_in, const int* in_sizes, int n_in,
                              void* d_out, int out_size) {
    (void)in_sizes; (void)n_in; (void)out_size;
    const float* x   = (const float*)d_in[0];   // [B, N, 13]
    const float* pos = (const float*)d_in[1];   // [B, N, 3]
    // d_in[2] = batch (int32) — always broadcast arange(B), recomputed directly
    const float* W1  = (const float*)d_in[3];   // [16, 64]
    const float* b1  = (const float*)d_in[4];   // [64]
    const float* W2  = (const float*)d_in[5];   // [64, 128]
    const float* b2  = (const float*)d_in[6];   // [128]
    float* out = (float*)d_out;

    fps_kernel<<<B_ * FPS_CTAS, FPS_THR>>>(pos, out);
    sa_kernel<<<(B_ * M_) / WPB, WPB * 32>>>(x, pos, W1, b1, W2, b2, out);
}